// round 2
// baseline (speedup 1.0000x reference)
#include <cuda_runtime.h>
#include <cstdint>

// Problem constants (match reference)
#define Bq      64
#define MAXREQ  64
#define SMAX    2048
#define PAGEq   128
#define Hq      32
#define KVHq    8
#define Gq      4          // H / KVH
#define HDq     128
#define SCALEq  0.08838834764831845f   // 128^-0.5

#define CHUNK   256        // tokens per split
#define NSPLIT  8          // SMAX / CHUNK
#define TILE    32         // tokens per smem tile
#define BDIM    128

#define KVSTRIDE    (KVHq*HDq)          // 1024 floats between tokens
#define BLKSTRIDE   (PAGEq*KVHq*HDq)    // 131072 floats per block

// split partials
__device__ float P_acc[Bq*KVHq*NSPLIT*Gq*HDq];   // 8 MB
__device__ float P_m[Bq*KVHq*NSPLIT*Gq];
__device__ float P_l[Bq*KVHq*NSPLIT*Gq];

// smem float offsets
#define KS0 0
#define KS1 4224            // 32 * 132
#define VS0 8448
#define VS1 12544           // +32*128
#define QOF 16640
#define POF 17152           // 4*32 p values
#define SOF 17280           // 4 scales
#define SMEM_FLOATS 17284
#define SMEM_BYTES  (SMEM_FLOATS*4)

__device__ __forceinline__ void cp16(uint32_t s, const void* g) {
    asm volatile("cp.async.cg.shared.global [%0], [%1], 16;\n" :: "r"(s), "l"(g));
}
__device__ __forceinline__ void cp_commit() { asm volatile("cp.async.commit_group;\n"); }
__device__ __forceinline__ void cp_wait0()  { asm volatile("cp.async.wait_group 0;\n"); }

__global__ __launch_bounds__(BDIM) void attn_split_kernel(
    const int* __restrict__ req_to_token,
    const int* __restrict__ req_pool,
    const int* __restrict__ seq_lens,
    const float* __restrict__ query,
    const float* __restrict__ k_cache,
    const float* __restrict__ v_cache)
{
    const int split = blockIdx.x;
    const int kvh   = blockIdx.y;
    const int b     = blockIdx.z;

    const int L  = seq_lens[b];
    const int c0 = split * CHUNK;
    if (c0 >= L) return;
    const int n_tok   = min(CHUNK, L - c0);
    const int n_tiles = (n_tok + TILE - 1) / TILE;

    extern __shared__ float sm[];
    const int tid  = threadIdx.x;
    const int g    = tid >> 5;
    const int lane = tid & 31;

    // ---- Q load (pre-scaled) : 4*128 floats ----
    #pragma unroll
    for (int j = 0; j < 4; j++) {
        int idx = tid + j * 128;                     // [0,512)
        sm[QOF + idx] = query[((long)b * Hq + kvh * Gq + (idx >> 7)) * HDq + (idx & 127)] * SCALEq;
    }

    // ---- block table: chunk spans exactly 2 pages ----
    const int req  = req_pool[b];
    const int pg0  = c0 >> 7;                        // first page of chunk
    const long blk0 = (long)(req_to_token[req * SMAX + pg0 * PAGEq] >> 7);
    const long blk1 = (long)(req_to_token[req * SMAX + (pg0 + 1) * PAGEq] >> 7);

    // ---- stage tile 'it' into buffer 'buf' ----
    auto stage = [&](int buf, int it) {
        const int t0   = it * TILE;
        const long blk = (t0 < 128) ? blk0 : blk1;
        const long off = blk * BLKSTRIDE + (long)(t0 & 127) * KVSTRIDE + kvh * HDq;
        const float* kb = k_cache + off;
        const float* vb = v_cache + off;
        uint32_t ks = (uint32_t)__cvta_generic_to_shared(sm + (buf ? KS1 : KS0));
        uint32_t vs = (uint32_t)__cvta_generic_to_shared(sm + (buf ? VS1 : VS0));
        #pragma unroll
        for (int j = 0; j < 8; j++) {
            int slot = tid + j * 128;                // [0,1024): 32 tok * 32 quads
            int t = slot >> 5, i = slot & 31;
            cp16(ks + (uint32_t)(t * 33 + i) * 16, kb + (long)t * KVSTRIDE + i * 4);
            cp16(vs + (uint32_t)(t * 32 + i) * 16, vb + (long)t * KVSTRIDE + i * 4);
        }
    };

    float m_run = -1e30f, l_run = 0.f;
    float a0 = 0.f, a1 = 0.f, a2 = 0.f, a3 = 0.f;    // phase-C acc, hd = tid

    stage(0, 0); cp_commit();

    for (int it = 0; it < n_tiles; it++) {
        cp_wait0();
        __syncthreads();                             // tile ready; prev phase C done
        if (it + 1 < n_tiles) { stage((it + 1) & 1, it + 1); cp_commit(); }

        // ---- phase A: warp g computes 32 scores ----
        const float4* K4 = (const float4*)(sm + ((it & 1) ? KS1 : KS0));
        const float4* Q4 = (const float4*)(sm + QOF);
        float s = 0.f;
        #pragma unroll
        for (int i = 0; i < 32; i++) {
            float4 k4 = K4[lane * 33 + i];
            float4 q4 = Q4[g * 32 + i];
            s += k4.x * q4.x + k4.y * q4.y + k4.z * q4.z + k4.w * q4.w;
        }
        int tok = c0 + it * TILE + lane;
        if (tok >= L) s = -1e30f;

        float mt = s;
        #pragma unroll
        for (int o = 16; o; o >>= 1) mt = fmaxf(mt, __shfl_xor_sync(0xffffffffu, mt, o));
        float m_new = fmaxf(m_run, mt);
        float p = __expf(s - m_new);
        float ps = p;
        #pragma unroll
        for (int o = 16; o; o >>= 1) ps += __shfl_xor_sync(0xffffffffu, ps, o);
        float csc = __expf(m_run - m_new);
        l_run = l_run * csc + ps;
        m_run = m_new;
        sm[POF + g * 32 + lane] = p;
        if (lane == 0) sm[SOF + g] = csc;
        __syncthreads();

        // ---- phase C: thread owns hd = tid, accumulate all 4 heads ----
        const float* V = sm + ((it & 1) ? VS1 : VS0);
        float c0s = sm[SOF + 0], c1s = sm[SOF + 1], c2s = sm[SOF + 2], c3s = sm[SOF + 3];
        a0 *= c0s; a1 *= c1s; a2 *= c2s; a3 *= c3s;
        #pragma unroll 8
        for (int t = 0; t < 32; t++) {
            float v = V[t * 128 + tid];
            a0 += sm[POF +       t] * v;
            a1 += sm[POF + 32  + t] * v;
            a2 += sm[POF + 64  + t] * v;
            a3 += sm[POF + 96  + t] * v;
        }
    }

    // ---- epilogue: write split partials ----
    const long base = ((long)(b * KVHq + kvh) * NSPLIT + split) * Gq;
    P_acc[(base + 0) * HDq + tid] = a0;
    P_acc[(base + 1) * HDq + tid] = a1;
    P_acc[(base + 2) * HDq + tid] = a2;
    P_acc[(base + 3) * HDq + tid] = a3;
    if (lane == 0) { P_m[base + g] = m_run; P_l[base + g] = l_run; }
}

__global__ __launch_bounds__(128) void combine_kernel(
    const int* __restrict__ seq_lens, float* __restrict__ out)
{
    const int h = blockIdx.x, b = blockIdx.y, hd = threadIdx.x;
    const int kvh = h >> 2, g = h & 3;
    const int L = seq_lens[b];
    const int ns = (L + CHUNK - 1) / CHUNK;

    float m = -1e30f, l = 0.f, acc = 0.f;
    const long base0 = (long)(b * KVHq + kvh) * NSPLIT * Gq + g;
    for (int s = 0; s < ns; s++) {
        long base = base0 + (long)s * Gq;
        float ms = P_m[base];
        float ls = P_l[base];
        float a  = P_acc[base * HDq + hd];
        float mn = fmaxf(m, ms);
        float e1 = __expf(m - mn), e2 = __expf(ms - mn);
        acc = acc * e1 + a * e2;
        l   = l   * e1 + ls * e2;
        m = mn;
    }
    out[((long)b * Hq + h) * HDq + hd] = acc / l;
}

extern "C" void kernel_launch(void* const* d_in, const int* in_sizes, int n_in,
                              void* d_out, int out_size)
{
    const int*   req_to_token = (const int*)d_in[0];
    const int*   req_pool     = (const int*)d_in[1];
    const int*   seq_lens     = (const int*)d_in[2];
    const float* query        = (const float*)d_in[3];
    const float* k_cache      = (const float*)d_in[4];
    const float* v_cache      = (const float*)d_in[5];
    float*       out          = (float*)d_out;

    cudaFuncSetAttribute(attn_split_kernel,
                         cudaFuncAttributeMaxDynamicSharedMemorySize, SMEM_BYTES);

    dim3 grid1(NSPLIT, KVHq, Bq);
    attn_split_kernel<<<grid1, BDIM, SMEM_BYTES>>>(
        req_to_token, req_pool, seq_lens, query, k_cache, v_cache);

    dim3 grid2(Hq, Bq);
    combine_kernel<<<grid2, 128>>>(seq_lens, out);
}

// round 3
// speedup vs baseline: 1.2253x; 1.2253x over previous
#include <cuda_runtime.h>
#include <cstdint>

// Problem constants
#define Bq      64
#define SMAX    2048
#define PAGEq   128
#define Hq      32
#define KVHq    8
#define Gq      4
#define HDq     128
#define SCALEq  0.08838834764831845f   // 128^-0.5

#define CHUNK   256        // tokens per CTA split
#define NSPLIT  8          // SMAX / CHUNK
#define WTOK    64         // tokens per warp
#define BDIM    128

#define KVSTRIDE  (KVHq*HDq)                 // floats between tokens
#define BLKSTRIDE ((long)PAGEq*KVHq*HDq)     // floats per KV block

// split partials
__device__ float P_acc[Bq*KVHq*NSPLIT*Gq*HDq];
__device__ float P_m[Bq*KVHq*NSPLIT*Gq];
__device__ float P_l[Bq*KVHq*NSPLIT*Gq];

// one butterfly stage of the 32-value cross-lane reduction
#define BFLY_STAGE(D)                                              \
    _Pragma("unroll")                                              \
    for (int j = 0; j < (D); j++) {                                \
        bool  hi   = (lane & (D)) != 0;                            \
        float send = hi ? r[j] : r[j + (D)];                       \
        float recv = __shfl_xor_sync(0xffffffffu, send, (D));      \
        float keep = hi ? r[j + (D)] : r[j];                       \
        r[j] = keep + recv;                                        \
    }

__global__ __launch_bounds__(BDIM) void attn_split_kernel(
    const int* __restrict__ req_to_token,
    const int* __restrict__ req_pool,
    const int* __restrict__ seq_lens,
    const float* __restrict__ query,
    const float* __restrict__ k_cache,
    const float* __restrict__ v_cache)
{
    const int split = blockIdx.x;
    const int kvh   = blockIdx.y;
    const int b     = blockIdx.z;

    const int L  = seq_lens[b];
    const int c0 = split * CHUNK;
    if (c0 >= L) return;

    const int w    = threadIdx.x >> 5;
    const int lane = threadIdx.x & 31;

    // ---- Q in registers, pre-scaled. lane owns d = 4*lane..4*lane+3 ----
    float4 q[4];
    {
        const float* Qb = query + ((long)b * Hq + kvh * Gq) * HDq + 4 * lane;
        #pragma unroll
        for (int h = 0; h < 4; h++) {
            float4 t = *(const float4*)(Qb + h * HDq);
            q[h] = make_float4(t.x * SCALEq, t.y * SCALEq, t.z * SCALEq, t.w * SCALEq);
        }
    }

    // ---- warp token range (stays within one KV page) ----
    const int warpStart = c0 + w * WTOK;
    const int req  = req_pool[b];
    const long blk = (long)(req_to_token[req * SMAX + (warpStart >> 7) * PAGEq] >> 7);
    const long off = blk * BLKSTRIDE + (long)(warpStart & 127) * KVSTRIDE + kvh * HDq + 4 * lane;
    const float* kp = k_cache + off;
    const float* vp = v_cache + off;

    int nt = L - warpStart;
    if (nt < 0) nt = 0;
    if (nt > WTOK) nt = WTOK;
    const int n_it = (nt + 7) >> 3;

    float4 out[4];
    #pragma unroll
    for (int h = 0; h < 4; h++) out[h] = make_float4(0.f, 0.f, 0.f, 0.f);
    float m_run = -1e30f, l_run = 0.f;   // state for head h = lane&3

    for (int it = 0; it < n_it; it++) {
        const float* kq = kp + (long)(it * 8) * KVSTRIDE;
        const float* vq = vp + (long)(it * 8) * KVSTRIDE;

        float4 k4[8];
        #pragma unroll
        for (int t = 0; t < 8; t++) k4[t] = *(const float4*)(kq + t * KVSTRIDE);
        float4 v4[8];
        #pragma unroll
        for (int t = 0; t < 8; t++) v4[t] = *(const float4*)(vq + t * KVSTRIDE);

        // per-lane partial dot for (token t, head h)
        float r[32];
        #pragma unroll
        for (int t = 0; t < 8; t++) {
            #pragma unroll
            for (int h = 0; h < 4; h++) {
                float a = k4[t].x * q[h].x;
                a = fmaf(k4[t].y, q[h].y, a);
                a = fmaf(k4[t].z, q[h].z, a);
                a = fmaf(k4[t].w, q[h].w, a);
                r[t * 4 + h] = a;
            }
        }

        // 32-value butterfly: lane l ends with full score for (t = l>>2, h = l&3)
        BFLY_STAGE(16) BFLY_STAGE(8) BFLY_STAGE(4) BFLY_STAGE(2) BFLY_STAGE(1)
        float s = r[0];

        const int tok = warpStart + it * 8 + (lane >> 2);
        if (tok >= L) s = -1e30f;

        // per-head max / sum over the 8 tokens (lanes stride 4 share a head)
        float mt = s;
        mt = fmaxf(mt, __shfl_xor_sync(0xffffffffu, mt, 4));
        mt = fmaxf(mt, __shfl_xor_sync(0xffffffffu, mt, 8));
        mt = fmaxf(mt, __shfl_xor_sync(0xffffffffu, mt, 16));
        float m_new = fmaxf(m_run, mt);
        float p  = __expf(s - m_new);
        float ps = p;
        ps += __shfl_xor_sync(0xffffffffu, ps, 4);
        ps += __shfl_xor_sync(0xffffffffu, ps, 8);
        ps += __shfl_xor_sync(0xffffffffu, ps, 16);
        float csc = __expf(m_run - m_new);
        l_run = l_run * csc + ps;
        m_run = m_new;

        // rescale accumulators (csc for head h lives in lane h, among others)
        #pragma unroll
        for (int h = 0; h < 4; h++) {
            float c = __shfl_sync(0xffffffffu, csc, h);
            out[h].x *= c; out[h].y *= c; out[h].z *= c; out[h].w *= c;
        }
        // P·V: broadcast p[t,h] from lane t*4+h
        #pragma unroll
        for (int t = 0; t < 8; t++) {
            #pragma unroll
            for (int h = 0; h < 4; h++) {
                float pp = __shfl_sync(0xffffffffu, p, t * 4 + h);
                out[h].x = fmaf(pp, v4[t].x, out[h].x);
                out[h].y = fmaf(pp, v4[t].y, out[h].y);
                out[h].z = fmaf(pp, v4[t].z, out[h].z);
                out[h].w = fmaf(pp, v4[t].w, out[h].w);
            }
        }
    }

    // ---- CTA-internal combine of the 4 warp sub-splits ----
    __shared__ float wacc[4][4][HDq];
    __shared__ float wm[4][4];
    __shared__ float wl[4][4];
    #pragma unroll
    for (int h = 0; h < 4; h++)
        *(float4*)&wacc[w][h][4 * lane] = out[h];
    if (lane < 4) { wm[w][lane] = m_run; wl[w][lane] = l_run; }
    __syncthreads();

    const int tid = threadIdx.x;
    const long base = ((long)(b * KVHq + kvh) * NSPLIT + split) * Gq;
    #pragma unroll
    for (int h = 0; h < 4; h++) {
        float m0 = wm[0][h], m1 = wm[1][h], m2 = wm[2][h], m3 = wm[3][h];
        float M = fmaxf(fmaxf(m0, m1), fmaxf(m2, m3));
        float e0 = __expf(m0 - M), e1 = __expf(m1 - M);
        float e2 = __expf(m2 - M), e3 = __expf(m3 - M);
        float acc = e0 * wacc[0][h][tid] + e1 * wacc[1][h][tid]
                  + e2 * wacc[2][h][tid] + e3 * wacc[3][h][tid];
        P_acc[(base + h) * HDq + tid] = acc;
        if (tid == 0) {
            P_m[base + h] = M;
            P_l[base + h] = e0 * wl[0][h] + e1 * wl[1][h] + e2 * wl[2][h] + e3 * wl[3][h];
        }
    }
}

__global__ __launch_bounds__(128) void combine_kernel(
    const int* __restrict__ seq_lens, float* __restrict__ out)
{
    const int h = blockIdx.x, b = blockIdx.y, hd = threadIdx.x;
    const int kvh = h >> 2, g = h & 3;
    const int L  = seq_lens[b];
    const int ns = (L + CHUNK - 1) / CHUNK;

    const long base0 = ((long)(b * KVHq + kvh) * NSPLIT) * Gq + g;

    // pass 1: batched m/l loads (independent -> high MLP)
    float ms[NSPLIT], ls[NSPLIT];
    #pragma unroll
    for (int s = 0; s < NSPLIT; s++) {
        bool v = s < ns;
        long base = base0 + (long)s * Gq;
        ms[s] = v ? P_m[base] : -1e30f;
        ls[s] = v ? P_l[base] : 0.f;
    }
    float M = -1e30f;
    #pragma unroll
    for (int s = 0; s < NSPLIT; s++) M = fmaxf(M, ms[s]);

    // pass 2: independent acc loads
    float acc = 0.f, l = 0.f;
    #pragma unroll
    for (int s = 0; s < NSPLIT; s++) {
        float e = __expf(ms[s] - M);
        l += e * ls[s];
        float a = (s < ns) ? P_acc[(base0 + (long)s * Gq) * HDq + hd] : 0.f;
        acc += e * a;
    }
    out[((long)b * Hq + h) * HDq + hd] = acc / l;
}

extern "C" void kernel_launch(void* const* d_in, const int* in_sizes, int n_in,
                              void* d_out, int out_size)
{
    const int*   req_to_token = (const int*)d_in[0];
    const int*   req_pool     = (const int*)d_in[1];
    const int*   seq_lens     = (const int*)d_in[2];
    const float* query        = (const float*)d_in[3];
    const float* k_cache      = (const float*)d_in[4];
    const float* v_cache      = (const float*)d_in[5];
    float*       out          = (float*)d_out;

    dim3 grid1(NSPLIT, KVHq, Bq);
    attn_split_kernel<<<grid1, BDIM>>>(
        req_to_token, req_pool, seq_lens, query, k_cache, v_cache);

    dim3 grid2(Hq, Bq);
    combine_kernel<<<grid2, 128>>>(seq_lens, out);
}

// round 4
// speedup vs baseline: 1.2284x; 1.0025x over previous
#include <cuda_runtime.h>
#include <cstdint>

// Problem constants
#define Bq      64
#define SMAX    2048
#define PAGEq   128
#define Hq      32
#define KVHq    8
#define Gq      4
#define HDq     128
#define SCALEq  0.08838834764831845f   // 128^-0.5

#define CHUNK   256        // tokens per CTA split
#define NSPLIT  8          // SMAX / CHUNK
#define WTOK    64         // tokens per warp
#define BDIM    128

#define KVSTRIDE  (KVHq*HDq)                 // floats between tokens
#define BLKSTRIDE ((long)PAGEq*KVHq*HDq)     // floats per KV block

// split partials + completion counters
__device__ float P_acc[Bq*KVHq*NSPLIT*Gq*HDq];
__device__ float P_m[Bq*KVHq*NSPLIT*Gq];
__device__ float P_l[Bq*KVHq*NSPLIT*Gq];
__device__ int   P_cnt[Bq*KVHq];             // zero-init; reset by combiner each launch

__device__ __forceinline__ float ldcg(const float* p) {
    float v; asm volatile("ld.global.cg.f32 %0, [%1];" : "=f"(v) : "l"(p)); return v;
}

// one butterfly stage of the 32-value cross-lane reduction
#define BFLY_STAGE(D)                                              \
    _Pragma("unroll")                                              \
    for (int j = 0; j < (D); j++) {                                \
        bool  hi   = (lane & (D)) != 0;                            \
        float send = hi ? r[j] : r[j + (D)];                       \
        float recv = __shfl_xor_sync(0xffffffffu, send, (D));      \
        float keep = hi ? r[j + (D)] : r[j];                       \
        r[j] = keep + recv;                                        \
    }

__global__ __launch_bounds__(BDIM) void attn_split_kernel(
    const int* __restrict__ req_to_token,
    const int* __restrict__ req_pool,
    const int* __restrict__ seq_lens,
    const float* __restrict__ query,
    const float* __restrict__ k_cache,
    const float* __restrict__ v_cache,
    float* __restrict__ outp)
{
    const int split = blockIdx.x;
    const int kvh   = blockIdx.y;
    const int b     = blockIdx.z;

    const int L  = seq_lens[b];
    const int c0 = split * CHUNK;
    if (c0 >= L) return;
    const int ns = (L + CHUNK - 1) / CHUNK;     // active splits for this (b,kvh)

    const int w    = threadIdx.x >> 5;
    const int lane = threadIdx.x & 31;
    const int tid  = threadIdx.x;

    // ---- Q in registers, pre-scaled. lane owns d = 4*lane..4*lane+3 ----
    float4 q[4];
    {
        const float* Qb = query + ((long)b * Hq + kvh * Gq) * HDq + 4 * lane;
        #pragma unroll
        for (int h = 0; h < 4; h++) {
            float4 t = *(const float4*)(Qb + h * HDq);
            q[h] = make_float4(t.x * SCALEq, t.y * SCALEq, t.z * SCALEq, t.w * SCALEq);
        }
    }

    // ---- warp token range (stays within one KV page) ----
    const int warpStart = c0 + w * WTOK;
    const int req  = req_pool[b];
    const long blk = (long)(req_to_token[req * SMAX + (warpStart >> 7) * PAGEq] >> 7);
    const long off = blk * BLKSTRIDE + (long)(warpStart & 127) * KVSTRIDE + kvh * HDq + 4 * lane;
    const float* kp = k_cache + off;
    const float* vp = v_cache + off;

    int nt = L - warpStart;
    if (nt < 0) nt = 0;
    if (nt > WTOK) nt = WTOK;
    const int n_it = (nt + 7) >> 3;

    float4 out[4];
    #pragma unroll
    for (int h = 0; h < 4; h++) out[h] = make_float4(0.f, 0.f, 0.f, 0.f);
    float m_run = -1e30f, l_run = 0.f;   // state for head h = lane&3

    for (int it = 0; it < n_it; it++) {
        const float* kq = kp + (long)(it * 8) * KVSTRIDE;
        const float* vq = vp + (long)(it * 8) * KVSTRIDE;

        float4 k4[8];
        #pragma unroll
        for (int t = 0; t < 8; t++) k4[t] = __ldcs((const float4*)(kq + t * KVSTRIDE));
        float4 v4[8];
        #pragma unroll
        for (int t = 0; t < 8; t++) v4[t] = __ldcs((const float4*)(vq + t * KVSTRIDE));

        // per-lane partial dot for (token t, head h)
        float r[32];
        #pragma unroll
        for (int t = 0; t < 8; t++) {
            #pragma unroll
            for (int h = 0; h < 4; h++) {
                float a = k4[t].x * q[h].x;
                a = fmaf(k4[t].y, q[h].y, a);
                a = fmaf(k4[t].z, q[h].z, a);
                a = fmaf(k4[t].w, q[h].w, a);
                r[t * 4 + h] = a;
            }
        }

        // 32-value butterfly: lane l ends with full score for (t = l>>2, h = l&3)
        BFLY_STAGE(16) BFLY_STAGE(8) BFLY_STAGE(4) BFLY_STAGE(2) BFLY_STAGE(1)
        float s = r[0];

        const int tok = warpStart + it * 8 + (lane >> 2);
        if (tok >= L) s = -1e30f;

        // per-head max / sum over the 8 tokens (lanes stride 4 share a head)
        float mt = s;
        mt = fmaxf(mt, __shfl_xor_sync(0xffffffffu, mt, 4));
        mt = fmaxf(mt, __shfl_xor_sync(0xffffffffu, mt, 8));
        mt = fmaxf(mt, __shfl_xor_sync(0xffffffffu, mt, 16));
        float m_new = fmaxf(m_run, mt);
        float p  = __expf(s - m_new);
        float ps = p;
        ps += __shfl_xor_sync(0xffffffffu, ps, 4);
        ps += __shfl_xor_sync(0xffffffffu, ps, 8);
        ps += __shfl_xor_sync(0xffffffffu, ps, 16);
        float csc = __expf(m_run - m_new);
        l_run = l_run * csc + ps;
        m_run = m_new;

        // rescale accumulators (csc for head h lives in lane h)
        #pragma unroll
        for (int h = 0; h < 4; h++) {
            float c = __shfl_sync(0xffffffffu, csc, h);
            out[h].x *= c; out[h].y *= c; out[h].z *= c; out[h].w *= c;
        }
        // P·V: broadcast p[t,h] from lane t*4+h
        #pragma unroll
        for (int t = 0; t < 8; t++) {
            #pragma unroll
            for (int h = 0; h < 4; h++) {
                float pp = __shfl_sync(0xffffffffu, p, t * 4 + h);
                out[h].x = fmaf(pp, v4[t].x, out[h].x);
                out[h].y = fmaf(pp, v4[t].y, out[h].y);
                out[h].z = fmaf(pp, v4[t].z, out[h].z);
                out[h].w = fmaf(pp, v4[t].w, out[h].w);
            }
        }
    }

    // ---- CTA-internal combine of the 4 warp sub-splits ----
    __shared__ float wacc[4][4][HDq];
    __shared__ float wm[4][4];
    __shared__ float wl[4][4];
    __shared__ int   s_last;
    #pragma unroll
    for (int h = 0; h < 4; h++)
        *(float4*)&wacc[w][h][4 * lane] = out[h];
    if (lane < 4) { wm[w][lane] = m_run; wl[w][lane] = l_run; }
    __syncthreads();

    const int  gidx = b * KVHq + kvh;
    const long base = (long)gidx * NSPLIT * Gq + (long)split * Gq;
    #pragma unroll
    for (int h = 0; h < 4; h++) {
        float m0 = wm[0][h], m1 = wm[1][h], m2 = wm[2][h], m3 = wm[3][h];
        float M = fmaxf(fmaxf(m0, m1), fmaxf(m2, m3));
        float e0 = __expf(m0 - M), e1 = __expf(m1 - M);
        float e2 = __expf(m2 - M), e3 = __expf(m3 - M);
        float acc = e0 * wacc[0][h][tid] + e1 * wacc[1][h][tid]
                  + e2 * wacc[2][h][tid] + e3 * wacc[3][h][tid];
        P_acc[(base + h) * HDq + tid] = acc;
        if (tid == 0) {
            P_m[base + h] = M;
            P_l[base + h] = e0 * wl[0][h] + e1 * wl[1][h] + e2 * wl[2][h] + e3 * wl[3][h];
        }
    }

    // ---- last-CTA-done global combine for this (b,kvh) ----
    __threadfence();
    if (tid == 0) {
        int old = atomicAdd(&P_cnt[gidx], 1);
        s_last = (old == ns - 1);
    }
    __syncthreads();
    if (!s_last) return;
    if (tid == 0) P_cnt[gidx] = 0;          // reset for next graph replay

    const long base0 = (long)gidx * NSPLIT * Gq;
    #pragma unroll
    for (int h = 0; h < 4; h++) {
        float ms[NSPLIT], ls[NSPLIT];
        #pragma unroll
        for (int s = 0; s < NSPLIT; s++) {
            bool v = s < ns;
            ms[s] = v ? ldcg(&P_m[base0 + s * Gq + h]) : -1e30f;
            ls[s] = v ? ldcg(&P_l[base0 + s * Gq + h]) : 0.f;
        }
        float M = -1e30f;
        #pragma unroll
        for (int s = 0; s < NSPLIT; s++) M = fmaxf(M, ms[s]);
        float acc = 0.f, l = 0.f;
        #pragma unroll
        for (int s = 0; s < NSPLIT; s++) {
            float e = __expf(ms[s] - M);
            l += e * ls[s];
            float a = (s < ns) ? ldcg(&P_acc[(base0 + s * Gq + h) * HDq + tid]) : 0.f;
            acc += e * a;
        }
        outp[((long)b * Hq + kvh * Gq + h) * HDq + tid] = acc / l;
    }
}

extern "C" void kernel_launch(void* const* d_in, const int* in_sizes, int n_in,
                              void* d_out, int out_size)
{
    const int*   req_to_token = (const int*)d_in[0];
    const int*   req_pool     = (const int*)d_in[1];
    const int*   seq_lens     = (const int*)d_in[2];
    const float* query        = (const float*)d_in[3];
    const float* k_cache      = (const float*)d_in[4];
    const float* v_cache      = (const float*)d_in[5];
    float*       out          = (float*)d_out;

    dim3 grid1(NSPLIT, KVHq, Bq);
    attn_split_kernel<<<grid1, BDIM>>>(
        req_to_token, req_pool, seq_lens, query, k_cache, v_cache, out);
}

// round 5
// speedup vs baseline: 1.2347x; 1.0051x over previous
#include <cuda_runtime.h>
#include <cstdint>

// Problem constants
#define Bq      64
#define SMAX    2048
#define PAGEq   128
#define Hq      32
#define KVHq    8
#define Gq      4
#define HDq     128
#define SCALEq  0.08838834764831845f   // 128^-0.5

#define CHUNK   256        // tokens per CTA split
#define NSPLIT  8          // SMAX / CHUNK
#define WTOK    64         // tokens per warp
#define BDIM    128

#define KVSTRIDE  (KVHq*HDq)                 // floats between tokens
#define BLKSTRIDE ((long)PAGEq*KVHq*HDq)     // floats per KV block

// split partials + completion counters
__device__ float P_acc[Bq*KVHq*NSPLIT*Gq*HDq];
__device__ float P_m[Bq*KVHq*NSPLIT*Gq];
__device__ float P_l[Bq*KVHq*NSPLIT*Gq];
__device__ int   P_cnt[Bq*KVHq];             // zero-init; reset by combiner each launch

__device__ __forceinline__ float ldcg(const float* p) {
    float v; asm volatile("ld.global.cg.f32 %0, [%1];" : "=f"(v) : "l"(p)); return v;
}
__device__ __forceinline__ void cp16(uint32_t s, const void* g) {
    asm volatile("cp.async.cg.shared.global [%0], [%1], 16;\n" :: "r"(s), "l"(g));
}
__device__ __forceinline__ void cp_commit() { asm volatile("cp.async.commit_group;\n"); }
__device__ __forceinline__ void cp_wait1()  { asm volatile("cp.async.wait_group 1;\n"); }

// one butterfly stage of the 32-value cross-lane reduction
#define BFLY_STAGE(D)                                              \
    _Pragma("unroll")                                              \
    for (int j = 0; j < (D); j++) {                                \
        bool  hi   = (lane & (D)) != 0;                            \
        float send = hi ? r[j] : r[j + (D)];                       \
        float recv = __shfl_xor_sync(0xffffffffu, send, (D));      \
        float keep = hi ? r[j + (D)] : r[j];                       \
        r[j] = keep + recv;                                        \
    }

__global__ __launch_bounds__(BDIM, 5) void attn_split_kernel(
    const int* __restrict__ req_to_token,
    const int* __restrict__ req_pool,
    const int* __restrict__ seq_lens,
    const float* __restrict__ query,
    const float* __restrict__ k_cache,
    const float* __restrict__ v_cache,
    float* __restrict__ outp)
{
    // per-warp V staging (double buffer); overlaid by warp-combine buffers after the loop
    __shared__ float smbuf[4][2][8 * HDq];   // 32 KB
    __shared__ int   s_last;

    const int split = blockIdx.x;
    const int kvh   = blockIdx.y;
    const int b     = blockIdx.z;

    const int L  = seq_lens[b];
    const int c0 = split * CHUNK;
    if (c0 >= L) return;
    const int ns = (L + CHUNK - 1) / CHUNK;

    const int w    = threadIdx.x >> 5;
    const int lane = threadIdx.x & 31;
    const int tid  = threadIdx.x;

    // ---- Q in registers, pre-scaled. lane owns d = 4*lane..4*lane+3 ----
    float4 q[4];
    {
        const float* Qb = query + ((long)b * Hq + kvh * Gq) * HDq + 4 * lane;
        #pragma unroll
        for (int h = 0; h < 4; h++) {
            float4 t = *(const float4*)(Qb + h * HDq);
            q[h] = make_float4(t.x * SCALEq, t.y * SCALEq, t.z * SCALEq, t.w * SCALEq);
        }
    }

    // ---- warp token range (stays within one KV page) ----
    const int warpStart = c0 + w * WTOK;
    const int req  = req_pool[b];
    const long blk = (long)(req_to_token[req * SMAX + (warpStart >> 7) * PAGEq] >> 7);
    const long off = blk * BLKSTRIDE + (long)(warpStart & 127) * KVSTRIDE + kvh * HDq + 4 * lane;
    const float* kp = k_cache + off;
    const float* vp = v_cache + off;

    int nt = L - warpStart;
    if (nt < 0) nt = 0;
    if (nt > WTOK) nt = WTOK;
    const int n_it = (nt + 7) >> 3;

    // smem addresses for this lane's V slices
    const uint32_t vs0 = (uint32_t)__cvta_generic_to_shared(&smbuf[w][0][4 * lane]);
    const uint32_t vs1 = (uint32_t)__cvta_generic_to_shared(&smbuf[w][1][4 * lane]);

    // stage V group 'it' into buffer 'buf' (lane-local: lane writes its own 16B/token)
    auto stageV = [&](int buf, int it) {
        const float* vq = vp + (long)(it * 8) * KVSTRIDE;
        uint32_t d = buf ? vs1 : vs0;
        #pragma unroll
        for (int t = 0; t < 8; t++)
            cp16(d + (uint32_t)(t * HDq) * 4, vq + (long)t * KVSTRIDE);
    };

    float4 out[4];
    #pragma unroll
    for (int h = 0; h < 4; h++) out[h] = make_float4(0.f, 0.f, 0.f, 0.f);
    float m_run = -1e30f, l_run = 0.f;   // state for head h = lane&3

    if (n_it > 0) { stageV(0, 0); cp_commit(); }

    for (int it = 0; it < n_it; it++) {
        // K group in registers
        const float* kq = kp + (long)(it * 8) * KVSTRIDE;
        float4 k4[8];
        #pragma unroll
        for (int t = 0; t < 8; t++) k4[t] = __ldcs((const float4*)(kq + t * KVSTRIDE));

        // prefetch next V group (always commit so wait_group 1 tracks correctly)
        if (it + 1 < n_it) stageV((it + 1) & 1, it + 1);
        cp_commit();

        // per-lane partial dot for (token t, head h)
        float r[32];
        #pragma unroll
        for (int t = 0; t < 8; t++) {
            #pragma unroll
            for (int h = 0; h < 4; h++) {
                float a = k4[t].x * q[h].x;
                a = fmaf(k4[t].y, q[h].y, a);
                a = fmaf(k4[t].z, q[h].z, a);
                a = fmaf(k4[t].w, q[h].w, a);
                r[t * 4 + h] = a;
            }
        }

        // 32-value butterfly: lane l ends with score for (t = l>>2, h = l&3)
        BFLY_STAGE(16) BFLY_STAGE(8) BFLY_STAGE(4) BFLY_STAGE(2) BFLY_STAGE(1)
        float s = r[0];

        const int tok = warpStart + it * 8 + (lane >> 2);
        if (tok >= L) s = -1e30f;

        // per-head max / sum over the 8 tokens (lanes stride 4 share a head)
        float mt = s;
        mt = fmaxf(mt, __shfl_xor_sync(0xffffffffu, mt, 4));
        mt = fmaxf(mt, __shfl_xor_sync(0xffffffffu, mt, 8));
        mt = fmaxf(mt, __shfl_xor_sync(0xffffffffu, mt, 16));
        float m_new = fmaxf(m_run, mt);
        float p  = __expf(s - m_new);
        float ps = p;
        ps += __shfl_xor_sync(0xffffffffu, ps, 4);
        ps += __shfl_xor_sync(0xffffffffu, ps, 8);
        ps += __shfl_xor_sync(0xffffffffu, ps, 16);
        float csc = __expf(m_run - m_new);
        l_run = l_run * csc + ps;
        m_run = m_new;

        // rescale accumulators
        #pragma unroll
        for (int h = 0; h < 4; h++) {
            float c = __shfl_sync(0xffffffffu, csc, h);
            out[h].x *= c; out[h].y *= c; out[h].z *= c; out[h].w *= c;
        }

        // V group is ready (previous group's cp.async drained; lane-local data)
        cp_wait1();
        const float* V = &smbuf[w][it & 1][4 * lane];
        #pragma unroll
        for (int t = 0; t < 8; t++) {
            float4 v4 = *(const float4*)(V + t * HDq);
            #pragma unroll
            for (int h = 0; h < 4; h++) {
                float pp = __shfl_sync(0xffffffffu, p, t * 4 + h);
                out[h].x = fmaf(pp, v4.x, out[h].x);
                out[h].y = fmaf(pp, v4.y, out[h].y);
                out[h].z = fmaf(pp, v4.z, out[h].z);
                out[h].w = fmaf(pp, v4.w, out[h].w);
            }
        }
    }

    // ---- CTA-internal combine: overlay warp buffers on this warp's V smem ----
    float* wacc = &smbuf[w][0][0];            // [4][128]
    float* wml  = &smbuf[w][1][0];            // m[4], l[4]
    #pragma unroll
    for (int h = 0; h < 4; h++)
        *(float4*)&wacc[h * HDq + 4 * lane] = out[h];
    if (lane < 4) { wml[lane] = m_run; wml[8 + lane] = l_run; }
    __syncthreads();

    const int  gidx = b * KVHq + kvh;
    const long base = (long)gidx * NSPLIT * Gq + (long)split * Gq;
    #pragma unroll
    for (int h = 0; h < 4; h++) {
        float m0 = smbuf[0][1][h], m1 = smbuf[1][1][h];
        float m2 = smbuf[2][1][h], m3 = smbuf[3][1][h];
        float M = fmaxf(fmaxf(m0, m1), fmaxf(m2, m3));
        float e0 = __expf(m0 - M), e1 = __expf(m1 - M);
        float e2 = __expf(m2 - M), e3 = __expf(m3 - M);
        float acc = e0 * smbuf[0][0][h * HDq + tid] + e1 * smbuf[1][0][h * HDq + tid]
                  + e2 * smbuf[2][0][h * HDq + tid] + e3 * smbuf[3][0][h * HDq + tid];
        P_acc[(base + h) * HDq + tid] = acc;
        if (tid == 0) {
            P_m[base + h] = M;
            P_l[base + h] = e0 * smbuf[0][1][8 + h] + e1 * smbuf[1][1][8 + h]
                          + e2 * smbuf[2][1][8 + h] + e3 * smbuf[3][1][8 + h];
        }
    }

    // ---- last-CTA-done global combine for this (b,kvh) ----
    __threadfence();
    if (tid == 0) {
        int old = atomicAdd(&P_cnt[gidx], 1);
        s_last = (old == ns - 1);
    }
    __syncthreads();
    if (!s_last) return;
    if (tid == 0) P_cnt[gidx] = 0;          // reset for next graph replay

    const long base0 = (long)gidx * NSPLIT * Gq;
    #pragma unroll
    for (int h = 0; h < 4; h++) {
        float ms[NSPLIT], ls[NSPLIT];
        #pragma unroll
        for (int s = 0; s < NSPLIT; s++) {
            bool v = s < ns;
            ms[s] = v ? ldcg(&P_m[base0 + s * Gq + h]) : -1e30f;
            ls[s] = v ? ldcg(&P_l[base0 + s * Gq + h]) : 0.f;
        }
        float M = -1e30f;
        #pragma unroll
        for (int s = 0; s < NSPLIT; s++) M = fmaxf(M, ms[s]);
        float acc = 0.f, l = 0.f;
        #pragma unroll
        for (int s = 0; s < NSPLIT; s++) {
            float e = __expf(ms[s] - M);
            l += e * ls[s];
            float a = (s < ns) ? ldcg(&P_acc[(base0 + s * Gq + h) * HDq + tid]) : 0.f;
            acc += e * a;
        }
        outp[((long)b * Hq + kvh * Gq + h) * HDq + tid] = acc / l;
    }
}

extern "C" void kernel_launch(void* const* d_in, const int* in_sizes, int n_in,
                              void* d_out, int out_size)
{
    const int*   req_to_token = (const int*)d_in[0];
    const int*   req_pool     = (const int*)d_in[1];
    const int*   seq_lens     = (const int*)d_in[2];
    const float* query        = (const float*)d_in[3];
    const float* k_cache      = (const float*)d_in[4];
    const float* v_cache      = (const float*)d_in[5];
    float*       out          = (float*)d_out;

    dim3 grid1(NSPLIT, KVHq, Bq);
    attn_split_kernel<<<grid1, BDIM>>>(
        req_to_token, req_pool, seq_lens, query, k_cache, v_cache, out);
}